// round 12
// baseline (speedup 1.0000x reference)
#include <cuda_runtime.h>
#include <cstdint>
#include <cstddef>
#include <math.h>

// ---------------------------------------------------------------------------
// LSTM  I=256 H=512 O=10 B=64 T=2048  (fp32, f32x2 packed-FMA pipe)
// R12: R11 minus the h-staging phase. The recurrent GEMM reads h directly
//      from L2 via __ldcg (1 coalesced 128B load per warp per k), overlapped
//      under the 4096-cyc FMA2 floor by unroll-8 MLP. W stays pre-splatted
//      in smem. Everything else identical to the 18.4ms R11.
// ---------------------------------------------------------------------------

#define TSZ  2048
#define NCTA 128

typedef unsigned long long ull;

// scratch (__device__ globals are the sanctioned scratch mechanism)
__device__ float    g_xg[268435456];     // 1 GiB: [T][4H][B]  (2048*2048*64)
__device__ float    g_h[2 * 512 * 64];   // double-buffered h: [H][B]
__device__ float    g_bias[2048];        // b_ih + b_hh
__device__ unsigned g_count;             // chip-barrier monotonic counter

// ---- packed f32x2 helpers (Blackwell dual-fp32 pipe) ----------------------
__device__ __forceinline__ ull pk2(float a, float b) {
    ull r; asm("mov.b64 %0,{%1,%2};" : "=l"(r) : "f"(a), "f"(b)); return r;
}
__device__ __forceinline__ ull splat2(float a) {
    ull r; asm("mov.b64 %0,{%1,%1};" : "=l"(r) : "f"(a)); return r;
}
__device__ __forceinline__ ull fma2(ull a, ull b, ull c) {
    ull d; asm("fma.rn.f32x2 %0,%1,%2,%3;" : "=l"(d) : "l"(a), "l"(b), "l"(c));
    return d;
}
__device__ __forceinline__ void upk2(ull v, float& a, float& b) {
    asm("mov.b64 {%0,%1},%2;" : "=f"(a), "=f"(b) : "l"(v));
}

// fast activations (rel err ~1e-6; budget 1e-3)
__device__ __forceinline__ float fsig(float x) {
    return __fdividef(1.0f, 1.0f + __expf(-x));
}
__device__ __forceinline__ float ftanh(float x) {
    return 1.0f - __fdividef(2.0f, __expf(2.0f * x) + 1.0f);
}

// ---------------------------------------------------------------------------
__global__ void k_init(const float* __restrict__ bih, const float* __restrict__ bhh) {
    int tid = blockIdx.x * blockDim.x + threadIdx.x;
    int nt  = gridDim.x * blockDim.x;
    if (tid < 2048) g_bias[tid] = bih[tid] + bhh[tid];
    for (int i = tid; i < 2 * 512 * 64; i += nt) g_h[i] = 0.0f;
    if (tid == 0) g_count = 0u;
}

// ---------------------------------------------------------------------------
// Phase 1: xg[t][row][b] = sum_i W_ih[row][i] * x[b][t][i] + bias[row]
// (unchanged -- passing since R5)
// ---------------------------------------------------------------------------
__global__ void __launch_bounds__(256) k_inproj(const float* __restrict__ x,
                                                const float* __restrict__ Wih) {
    __shared__ __align__(16) float As[16 * 132];
    __shared__ __align__(16) float Bs[16 * 66];

    const int tid = threadIdx.x;
    const int bx  = blockIdx.x;
    const int t   = blockIdx.y;
    const int tr  = tid >> 4, tc = tid & 15;
    const int r0  = tr * 8,  c0 = tc * 4;
    const int kkg = tid & 3;
    const int bb  = tid >> 2;

    ull acc[8][2];
#pragma unroll
    for (int i = 0; i < 8; i++) { acc[i][0] = 0ull; acc[i][1] = 0ull; }

    for (int k0 = 0; k0 < 256; k0 += 16) {
#pragma unroll
        for (int j = 0; j < 2; j++) {
            int rr = (tid >> 2) + j * 64;
            float4 av = *(const float4*)(Wih + (size_t)(bx * 128 + rr) * 256 + k0 + kkg * 4);
            As[(kkg * 4 + 0) * 132 + rr] = av.x;
            As[(kkg * 4 + 1) * 132 + rr] = av.y;
            As[(kkg * 4 + 2) * 132 + rr] = av.z;
            As[(kkg * 4 + 3) * 132 + rr] = av.w;
        }
        {
            float4 bv = *(const float4*)(x + ((size_t)bb * 2048 + t) * 256 + k0 + kkg * 4);
            Bs[(kkg * 4 + 0) * 66 + bb] = bv.x;
            Bs[(kkg * 4 + 1) * 66 + bb] = bv.y;
            Bs[(kkg * 4 + 2) * 66 + bb] = bv.z;
            Bs[(kkg * 4 + 3) * 66 + bb] = bv.w;
        }
        __syncthreads();
#pragma unroll
        for (int k = 0; k < 16; k++) {
            float4 a0 = *(const float4*)&As[k * 132 + r0];
            float4 a1 = *(const float4*)&As[k * 132 + r0 + 4];
            ull b0 = *(const ull*)&Bs[k * 66 + c0];
            ull b1 = *(const ull*)&Bs[k * 66 + c0 + 2];
            ull sp;
            sp = splat2(a0.x); acc[0][0] = fma2(sp, b0, acc[0][0]); acc[0][1] = fma2(sp, b1, acc[0][1]);
            sp = splat2(a0.y); acc[1][0] = fma2(sp, b0, acc[1][0]); acc[1][1] = fma2(sp, b1, acc[1][1]);
            sp = splat2(a0.z); acc[2][0] = fma2(sp, b0, acc[2][0]); acc[2][1] = fma2(sp, b1, acc[2][1]);
            sp = splat2(a0.w); acc[3][0] = fma2(sp, b0, acc[3][0]); acc[3][1] = fma2(sp, b1, acc[3][1]);
            sp = splat2(a1.x); acc[4][0] = fma2(sp, b0, acc[4][0]); acc[4][1] = fma2(sp, b1, acc[4][1]);
            sp = splat2(a1.y); acc[5][0] = fma2(sp, b0, acc[5][0]); acc[5][1] = fma2(sp, b1, acc[5][1]);
            sp = splat2(a1.z); acc[6][0] = fma2(sp, b0, acc[6][0]); acc[6][1] = fma2(sp, b1, acc[6][1]);
            sp = splat2(a1.w); acc[7][0] = fma2(sp, b0, acc[7][0]); acc[7][1] = fma2(sp, b1, acc[7][1]);
        }
        __syncthreads();
    }
#pragma unroll
    for (int i = 0; i < 8; i++) {
        int row = bx * 128 + r0 + i;
        float bias = g_bias[row];
        float p0, p1, p2, p3;
        upk2(acc[i][0], p0, p1);
        upk2(acc[i][1], p2, p3);
        *(float4*)(g_xg + ((size_t)t * 2048 + row) * 64 + c0) =
            make_float4(p0 + bias, p1 + bias, p2 + bias, p3 + bias);
    }
}

// ---------------------------------------------------------------------------
// Phase 2: persistent recurrence, 128 CTAs x 256 threads, 1 CTA/SM.
// CTA owns 4 hidden units -> 16 gate rows (rl = unit*4 + gate).
// smem: Wt2 = pre-splatted {w,w} ull [512 k][16 rows]        = 64 KB
//       gp  = k-quarter partials [4][16][64]                 = 16 KB
// Warp (q = wid&3 k-quarter, ch = wid>>2 col-half): 16r x 32c x 128k.
// Lane (rg = lane>>3, cg = lane&7): 4 rows x 4 cols.
// Per k per warp: 2x LDS.128 (W, dedup'd) + 1x LDG.128 ldcg (h, coalesced
// 128B, lane-broadcast across row groups) + 8 FFMA2 per lane.
// h reads stream from L2 directly -- no staging phase, latency hidden by
// unroll-8 MLP under the 4096-cyc FMA2 floor.
// ---------------------------------------------------------------------------
__global__ void __launch_bounds__(256, 1) k_rec(const float* __restrict__ Whh) {
    extern __shared__ __align__(16) char smraw[];
    ull*   Wt2 = (ull*)smraw;                          // 512*16 ull = 65536 B
    float* gp  = (float*)(smraw + 65536);              // 4*16*64 fl = 16384 B

    const int tid  = threadIdx.x;
    const int h0   = blockIdx.x * 4;
    const int wid  = tid >> 5, lane = tid & 31;
    const int q    = wid & 3;                 // k-quarter
    const int ch   = wid >> 2;                // col half
    const int rg   = lane >> 3, cg = lane & 7;
    const int r0   = rg * 4;                  // 4 rows
    const int c0   = ch * 32 + cg * 4;        // 4 cols
    const int u2   = tid >> 6, b = tid & 63;  // cell-update mapping

    // fill pre-splatted W slab: Wt2[k*16 + rl] = {w,w},
    // w = Whh[(rl&3)*512 + h0 + (rl>>2)][k]
#pragma unroll
    for (int j = 0; j < 8; j++) {
        int flat = tid + j * 256;              // float4 idx 0..2047
        int rl = flat >> 7, k4 = flat & 127;
        int grw = (rl & 3) * 512 + h0 + (rl >> 2);
        float4 w4 = *(const float4*)(Whh + (size_t)grw * 512 + k4 * 4);
        Wt2[(k4 * 4 + 0) * 16 + rl] = splat2(w4.x);
        Wt2[(k4 * 4 + 1) * 16 + rl] = splat2(w4.y);
        Wt2[(k4 * 4 + 2) * 16 + rl] = splat2(w4.z);
        Wt2[(k4 * 4 + 3) * 16 + rl] = splat2(w4.w);
    }
    float cstate = 0.0f;
    __syncthreads();

    for (int s = 0; s < TSZ; s++) {
        const float* hin  = g_h + (s & 1) * 32768;
        float*       hout = g_h + ((s + 1) & 1) * 32768;

        // xg for this thread's cell: independent of h -> load before poll
        float xgi = __ldcs(g_xg + ((size_t)s * 2048 + 0 * 512 + h0 + u2) * 64 + b);
        float xgf = __ldcs(g_xg + ((size_t)s * 2048 + 1 * 512 + h0 + u2) * 64 + b);
        float xgg = __ldcs(g_xg + ((size_t)s * 2048 + 2 * 512 + h0 + u2) * 64 + b);
        float xgo = __ldcs(g_xg + ((size_t)s * 2048 + 3 * 512 + h0 + u2) * 64 + b);

        // ---- wait: all CTAs completed step s-1 --------------------------
        if (tid == 0) {
            const unsigned target = (unsigned)s * NCTA;
            unsigned v;
            do {
                asm volatile("ld.relaxed.gpu.global.u32 %0,[%1];"
                             : "=r"(v) : "l"(&g_count));
            } while (v < target);
            asm volatile("fence.acq_rel.gpu;" ::: "memory");
        }
        __syncthreads();

        // ---- GEMM: this warp's 128-k quarter, h streamed from L2 --------
        ull a00 = 0, a01 = 0, a10 = 0, a11 = 0;
        ull a20 = 0, a21 = 0, a30 = 0, a31 = 0;
        {
            const int kbeg = q * 128;
            const float* hp = hin + (size_t)kbeg * 64 + c0;
            const ull*   wp = Wt2 + kbeg * 16;
#pragma unroll 8
            for (int k = 0; k < 128; k++) {
                float4 h4 = __ldcg((const float4*)(hp + k * 64));
                ulonglong2 wa = *(const ulonglong2*)(wp + k * 16 + r0);     // rows r0,r0+1
                ulonglong2 wb = *(const ulonglong2*)(wp + k * 16 + r0 + 2); // rows r0+2,+3
                ull hx = pk2(h4.x, h4.y);
                ull hy = pk2(h4.z, h4.w);
                a00 = fma2(wa.x, hx, a00); a01 = fma2(wa.x, hy, a01);
                a10 = fma2(wa.y, hx, a10); a11 = fma2(wa.y, hy, a11);
                a20 = fma2(wb.x, hx, a20); a21 = fma2(wb.x, hy, a21);
                a30 = fma2(wb.y, hx, a30); a31 = fma2(wb.y, hy, a31);
            }
        }
        // write k-quarter partials
        {
            float* gq = gp + (q * 16) * 64;
            *(ulonglong2*)(gq + (r0 + 0) * 64 + c0) = make_ulonglong2(a00, a01);
            *(ulonglong2*)(gq + (r0 + 1) * 64 + c0) = make_ulonglong2(a10, a11);
            *(ulonglong2*)(gq + (r0 + 2) * 64 + c0) = make_ulonglong2(a20, a21);
            *(ulonglong2*)(gq + (r0 + 3) * 64 + c0) = make_ulonglong2(a30, a31);
        }
        __syncthreads();

        // ---- reduce partials + cell update (one cell per thread) --------
        {
            int rI = u2 * 4 + 0, rF = u2 * 4 + 1, rG = u2 * 4 + 2, rO = u2 * 4 + 3;
            float gi = xgi, gf = xgf, gg = xgg, go = xgo;
#pragma unroll
            for (int qq = 0; qq < 4; qq++) {
                const float* gq = gp + (qq * 16) * 64;
                gi += gq[rI * 64 + b];
                gf += gq[rF * 64 + b];
                gg += gq[rG * 64 + b];
                go += gq[rO * 64 + b];
            }
            float ig = fsig(gi), fg = fsig(gf), gt = ftanh(gg), og = fsig(go);
            cstate = fg * cstate + ig * gt;
            float hv = og * ftanh(cstate);
            asm volatile("st.global.cg.f32 [%0], %1;"
                         :: "l"(hout + (h0 + u2) * 64 + b), "f"(hv) : "memory");
        }
        __syncthreads();   // all hout stores issued (CTA order point)

        // ---- publish: bump global counter (no-return reduction) ---------
        if (tid == 0) {
            asm volatile("fence.acq_rel.gpu;" ::: "memory");
            asm volatile("red.relaxed.gpu.global.add.u32 [%0], %1;"
                         :: "l"(&g_count), "r"(1u) : "memory");
        }
    }
}

// ---------------------------------------------------------------------------
// FC head: out[b][o] = sum_h h_last[h][b] * W_fc[o][h] + b_fc[o]
// warp-per-output, shfl reduction. h_last = g_h buffer 0.
// ---------------------------------------------------------------------------
__global__ void __launch_bounds__(256) k_fc(const float* __restrict__ Wfc,
                                            const float* __restrict__ bfc,
                                            float* __restrict__ out) {
    int g    = blockIdx.x * 8 + (threadIdx.x >> 5);
    int lane = threadIdx.x & 31;
    int o = g >> 6, b = g & 63;
    float s = 0.0f;
#pragma unroll
    for (int j = 0; j < 16; j++) {
        int h = lane + j * 32;
        s += g_h[h * 64 + b] * Wfc[o * 512 + h];
    }
#pragma unroll
    for (int m = 16; m > 0; m >>= 1)
        s += __shfl_xor_sync(0xFFFFFFFFu, s, m);
    if (lane == 0) out[b * 10 + o] = s + bfc[o];
}

// ---------------------------------------------------------------------------
extern "C" void kernel_launch(void* const* d_in, const int* in_sizes, int n_in,
                              void* d_out, int out_size) {
    const float* x    = (const float*)d_in[0];
    const float* W_ih = (const float*)d_in[1];
    const float* W_hh = (const float*)d_in[2];
    const float* b_ih = (const float*)d_in[3];
    const float* b_hh = (const float*)d_in[4];
    const float* W_fc = (const float*)d_in[5];
    const float* b_fc = (const float*)d_in[6];
    float* out = (float*)d_out;

    const int SMEM_REC = 65536 + 16384;   // 81920 B
    cudaFuncSetAttribute(k_rec, cudaFuncAttributeMaxDynamicSharedMemorySize, SMEM_REC);

    k_init<<<64, 256>>>(b_ih, b_hh);
    k_inproj<<<dim3(16, 2048), 256>>>(x, W_ih);
    k_rec<<<NCTA, 256, SMEM_REC>>>(W_hh);
    k_fc<<<80, 256>>>(W_fc, b_fc, out);
}

// round 13
// speedup vs baseline: 1.7021x; 1.7021x over previous
#include <cuda_runtime.h>
#include <cstdint>
#include <cstddef>
#include <math.h>

// ---------------------------------------------------------------------------
// LSTM  I=256 H=512 O=10 B=64 T=2048  (fp32, f32x2 packed-FMA pipe)
// R13: R11 (18.4ms, proven) + TMA 4-chunk pipelined h staging.
//   - tid0 issues 4x32KB cp.async.bulk after the barrier poll; GEMM runs in
//     4 phases gated by per-chunk mbarriers -> only chunk 0's fill exposed.
//   - R12's in-loop L2 streaming reverted (latency-bound, regressed).
//   - tiles / partials / barrier / epilogue identical to R11.
// ---------------------------------------------------------------------------

#define TSZ  2048
#define NCTA 128

typedef unsigned long long ull;

// scratch (__device__ globals are the sanctioned scratch mechanism)
__device__ float    g_xg[268435456];     // 1 GiB: [T][4H][B]  (2048*2048*64)
__device__ float    g_h[2 * 512 * 64];   // double-buffered h: [H][B]
__device__ float    g_bias[2048];        // b_ih + b_hh
__device__ unsigned g_count;             // chip-barrier monotonic counter

// ---- packed f32x2 helpers (Blackwell dual-fp32 pipe) ----------------------
__device__ __forceinline__ ull splat2(float a) {
    ull r; asm("mov.b64 %0,{%1,%1};" : "=l"(r) : "f"(a)); return r;
}
__device__ __forceinline__ ull fma2(ull a, ull b, ull c) {
    ull d; asm("fma.rn.f32x2 %0,%1,%2,%3;" : "=l"(d) : "l"(a), "l"(b), "l"(c));
    return d;
}
__device__ __forceinline__ void upk2(ull v, float& a, float& b) {
    asm("mov.b64 {%0,%1},%2;" : "=f"(a), "=f"(b) : "l"(v));
}

// fast activations (rel err ~1e-6; budget 1e-3)
__device__ __forceinline__ float fsig(float x) {
    return __fdividef(1.0f, 1.0f + __expf(-x));
}
__device__ __forceinline__ float ftanh(float x) {
    return 1.0f - __fdividef(2.0f, __expf(2.0f * x) + 1.0f);
}

// ---- smem / mbarrier / bulk-copy helpers ----------------------------------
__device__ __forceinline__ uint32_t s2u(const void* p) {
    uint32_t a;
    asm("{ .reg .u64 t; cvta.to.shared.u64 t, %1; cvt.u32.u64 %0, t; }"
        : "=r"(a) : "l"(p));
    return a;
}
__device__ __forceinline__ void mbar_init(uint32_t m, unsigned cnt) {
    asm volatile("mbarrier.init.shared.b64 [%0], %1;" :: "r"(m), "r"(cnt) : "memory");
}
__device__ __forceinline__ void mbar_expect_tx(uint32_t m, unsigned bytes) {
    asm volatile("mbarrier.arrive.expect_tx.shared.b64 _, [%0], %1;"
                 :: "r"(m), "r"(bytes) : "memory");
}
__device__ __forceinline__ void mbar_wait(uint32_t m, int phase) {
    asm volatile(
        "{\n\t.reg .pred P;\n\t"
        "LW_%=:\n\t"
        "mbarrier.try_wait.parity.acquire.cta.shared::cta.b64 P, [%0], %1, 0x989680;\n\t"
        "@P bra LD_%=;\n\t"
        "bra LW_%=;\n\t"
        "LD_%=:\n\t}"
        :: "r"(m), "r"(phase) : "memory");
}
__device__ __forceinline__ void bulk_g2s(uint32_t dst, const void* src,
                                         unsigned bytes, uint32_t mbar) {
    asm volatile(
        "cp.async.bulk.shared::cluster.global.mbarrier::complete_tx::bytes "
        "[%0], [%1], %2, [%3];"
        :: "r"(dst), "l"(src), "r"(bytes), "r"(mbar) : "memory");
}

// ---------------------------------------------------------------------------
__global__ void k_init(const float* __restrict__ bih, const float* __restrict__ bhh) {
    int tid = blockIdx.x * blockDim.x + threadIdx.x;
    int nt  = gridDim.x * blockDim.x;
    if (tid < 2048) g_bias[tid] = bih[tid] + bhh[tid];
    for (int i = tid; i < 2 * 512 * 64; i += nt) g_h[i] = 0.0f;
    if (tid == 0) g_count = 0u;
}

// ---------------------------------------------------------------------------
// Phase 1: xg[t][row][b] = sum_i W_ih[row][i] * x[b][t][i] + bias[row]
// (unchanged -- passing since R5)
// ---------------------------------------------------------------------------
__global__ void __launch_bounds__(256) k_inproj(const float* __restrict__ x,
                                                const float* __restrict__ Wih) {
    __shared__ __align__(16) float As[16 * 132];
    __shared__ __align__(16) float Bs[16 * 66];

    const int tid = threadIdx.x;
    const int bx  = blockIdx.x;
    const int t   = blockIdx.y;
    const int tr  = tid >> 4, tc = tid & 15;
    const int r0  = tr * 8,  c0 = tc * 4;
    const int kkg = tid & 3;
    const int bb  = tid >> 2;

    ull acc[8][2];
#pragma unroll
    for (int i = 0; i < 8; i++) { acc[i][0] = 0ull; acc[i][1] = 0ull; }

    for (int k0 = 0; k0 < 256; k0 += 16) {
#pragma unroll
        for (int j = 0; j < 2; j++) {
            int rr = (tid >> 2) + j * 64;
            float4 av = *(const float4*)(Wih + (size_t)(bx * 128 + rr) * 256 + k0 + kkg * 4);
            As[(kkg * 4 + 0) * 132 + rr] = av.x;
            As[(kkg * 4 + 1) * 132 + rr] = av.y;
            As[(kkg * 4 + 2) * 132 + rr] = av.z;
            As[(kkg * 4 + 3) * 132 + rr] = av.w;
        }
        {
            float4 bv = *(const float4*)(x + ((size_t)bb * 2048 + t) * 256 + k0 + kkg * 4);
            Bs[(kkg * 4 + 0) * 66 + bb] = bv.x;
            Bs[(kkg * 4 + 1) * 66 + bb] = bv.y;
            Bs[(kkg * 4 + 2) * 66 + bb] = bv.z;
            Bs[(kkg * 4 + 3) * 66 + bb] = bv.w;
        }
        __syncthreads();
#pragma unroll
        for (int k = 0; k < 16; k++) {
            float4 a0 = *(const float4*)&As[k * 132 + r0];
            float4 a1 = *(const float4*)&As[k * 132 + r0 + 4];
            ull b0 = *(const ull*)&Bs[k * 66 + c0];
            ull b1 = *(const ull*)&Bs[k * 66 + c0 + 2];
            ull sp;
            sp = splat2(a0.x); acc[0][0] = fma2(sp, b0, acc[0][0]); acc[0][1] = fma2(sp, b1, acc[0][1]);
            sp = splat2(a0.y); acc[1][0] = fma2(sp, b0, acc[1][0]); acc[1][1] = fma2(sp, b1, acc[1][1]);
            sp = splat2(a0.z); acc[2][0] = fma2(sp, b0, acc[2][0]); acc[2][1] = fma2(sp, b1, acc[2][1]);
            sp = splat2(a0.w); acc[3][0] = fma2(sp, b0, acc[3][0]); acc[3][1] = fma2(sp, b1, acc[3][1]);
            sp = splat2(a1.x); acc[4][0] = fma2(sp, b0, acc[4][0]); acc[4][1] = fma2(sp, b1, acc[4][1]);
            sp = splat2(a1.y); acc[5][0] = fma2(sp, b0, acc[5][0]); acc[5][1] = fma2(sp, b1, acc[5][1]);
            sp = splat2(a1.z); acc[6][0] = fma2(sp, b0, acc[6][0]); acc[6][1] = fma2(sp, b1, acc[6][1]);
            sp = splat2(a1.w); acc[7][0] = fma2(sp, b0, acc[7][0]); acc[7][1] = fma2(sp, b1, acc[7][1]);
        }
        __syncthreads();
    }
#pragma unroll
    for (int i = 0; i < 8; i++) {
        int row = bx * 128 + r0 + i;
        float bias = g_bias[row];
        float p0, p1, p2, p3;
        upk2(acc[i][0], p0, p1);
        upk2(acc[i][1], p2, p3);
        *(float4*)(g_xg + ((size_t)t * 2048 + row) * 64 + c0) =
            make_float4(p0 + bias, p1 + bias, p2 + bias, p3 + bias);
    }
}

// ---------------------------------------------------------------------------
// Phase 2: persistent recurrence, 128 CTAs x 256 threads, 1 CTA/SM.
// CTA owns 4 hidden units -> 16 gate rows (rl = unit*4 + gate).
// smem: Wt2 = pre-splatted {w,w} ull [512 k][16 rows]        = 64 KB
//       hs  = full h [512 k][64 b], TMA-filled in 4 chunks   = 128 KB
//       gp  = warp-group partials [4][16][64]                = 16 KB
// GEMM: 4 phases of 128 k, gated by per-chunk mbarriers. Within a phase,
// warp (q = wid&3) covers k-sub [q*32,+32), ch = wid>>2 col half.
// Lane (rg = lane>>3, cg = lane&7): 4 rows x 4 cols.
// Per k per warp: 2x LDS.128 (W, dedup) + 1x LDS.128 (h) + 8 FFMA2/lane.
// ---------------------------------------------------------------------------
__global__ void __launch_bounds__(256, 1) k_rec(const float* __restrict__ Whh) {
    extern __shared__ __align__(16) char smraw[];
    ull*   Wt2 = (ull*)smraw;                          // 512*16 ull = 65536 B
    float* hs  = (float*)(smraw + 65536);              // 512*64 fl  = 131072 B
    float* gp  = (float*)(smraw + 65536 + 131072);     // 4*16*64 fl = 16384 B
    __shared__ __align__(8) ull mbars[4];

    const int tid  = threadIdx.x;
    const int h0   = blockIdx.x * 4;
    const int wid  = tid >> 5, lane = tid & 31;
    const int q    = wid & 3;                 // k-sub within each chunk
    const int ch   = wid >> 2;                // col half
    const int rg   = lane >> 3, cg = lane & 7;
    const int r0   = rg * 4;                  // 4 rows
    const int c0   = ch * 32 + cg * 4;        // 4 cols
    const int u2   = tid >> 6, b = tid & 63;  // cell-update mapping

    const uint32_t hs_u = s2u(hs);

    // fill pre-splatted W slab: Wt2[k*16 + rl] = {w,w},
    // w = Whh[(rl&3)*512 + h0 + (rl>>2)][k]
#pragma unroll
    for (int j = 0; j < 8; j++) {
        int flat = tid + j * 256;              // float4 idx 0..2047
        int rl = flat >> 7, k4 = flat & 127;
        int grw = (rl & 3) * 512 + h0 + (rl >> 2);
        float4 w4 = *(const float4*)(Whh + (size_t)grw * 512 + k4 * 4);
        Wt2[(k4 * 4 + 0) * 16 + rl] = splat2(w4.x);
        Wt2[(k4 * 4 + 1) * 16 + rl] = splat2(w4.y);
        Wt2[(k4 * 4 + 2) * 16 + rl] = splat2(w4.z);
        Wt2[(k4 * 4 + 3) * 16 + rl] = splat2(w4.w);
    }
    if (tid == 0) {
#pragma unroll
        for (int p = 0; p < 4; p++) mbar_init(s2u(&mbars[p]), 1u);
    }
    float cstate = 0.0f;
    __syncthreads();

    for (int s = 0; s < TSZ; s++) {
        const float* hin  = g_h + (s & 1) * 32768;
        float*       hout = g_h + ((s + 1) & 1) * 32768;
        const int    ph   = s & 1;            // mbar parity (1 use per step)

        // xg for this thread's cell (independent of h; overlaps everything)
        float xgi = __ldcs(g_xg + ((size_t)s * 2048 + 0 * 512 + h0 + u2) * 64 + b);
        float xgf = __ldcs(g_xg + ((size_t)s * 2048 + 1 * 512 + h0 + u2) * 64 + b);
        float xgg = __ldcs(g_xg + ((size_t)s * 2048 + 2 * 512 + h0 + u2) * 64 + b);
        float xgo = __ldcs(g_xg + ((size_t)s * 2048 + 3 * 512 + h0 + u2) * 64 + b);

        // ---- tid0: wait for all CTAs (step s-1), then launch 4 TMA chunks
        if (tid == 0) {
            const unsigned target = (unsigned)s * NCTA;
            unsigned v;
            do {
                asm volatile("ld.relaxed.gpu.global.u32 %0,[%1];"
                             : "=r"(v) : "l"(&g_count));
            } while (v < target);
            asm volatile("fence.acq_rel.gpu;" ::: "memory");
            asm volatile("fence.proxy.async;" ::: "memory");
#pragma unroll
            for (int p = 0; p < 4; p++) {
                uint32_t m = s2u(&mbars[p]);
                mbar_expect_tx(m, 32768u);
                bulk_g2s(hs_u + p * 32768u, hin + p * 8192, 32768u, m);
            }
        }
        // (no __syncthreads: consumers gate on the chunk mbarriers)

        // ---- GEMM: 4 phases of 128 k; warp q takes 32 k per phase --------
        ull a00 = 0, a01 = 0, a10 = 0, a11 = 0;
        ull a20 = 0, a21 = 0, a30 = 0, a31 = 0;
#pragma unroll
        for (int p = 0; p < 4; p++) {
            mbar_wait(s2u(&mbars[p]), ph);
            const int kbeg = p * 128 + q * 32;
            const ull*   wp = Wt2 + kbeg * 16;
            const float* hp = hs + kbeg * 64 + c0;
#pragma unroll
            for (int k = 0; k < 32; k++) {
                ulonglong2 wa = *(const ulonglong2*)(wp + k * 16 + r0);     // rows r0,r0+1
                ulonglong2 wb = *(const ulonglong2*)(wp + k * 16 + r0 + 2); // rows r0+2,+3
                ulonglong2 hv = *(const ulonglong2*)(hp + k * 64);          // cols c0..+3
                a00 = fma2(wa.x, hv.x, a00); a01 = fma2(wa.x, hv.y, a01);
                a10 = fma2(wa.y, hv.x, a10); a11 = fma2(wa.y, hv.y, a11);
                a20 = fma2(wb.x, hv.x, a20); a21 = fma2(wb.x, hv.y, a21);
                a30 = fma2(wb.y, hv.x, a30); a31 = fma2(wb.y, hv.y, a31);
            }
        }
        // write warp-group partials
        {
            float* gq = gp + (q * 16) * 64;
            *(ulonglong2*)(gq + (r0 + 0) * 64 + c0) = make_ulonglong2(a00, a01);
            *(ulonglong2*)(gq + (r0 + 1) * 64 + c0) = make_ulonglong2(a10, a11);
            *(ulonglong2*)(gq + (r0 + 2) * 64 + c0) = make_ulonglong2(a20, a21);
            *(ulonglong2*)(gq + (r0 + 3) * 64 + c0) = make_ulonglong2(a30, a31);
        }
        __syncthreads();

        // ---- reduce partials + cell update (one cell per thread) --------
        {
            int rI = u2 * 4 + 0, rF = u2 * 4 + 1, rG = u2 * 4 + 2, rO = u2 * 4 + 3;
            float gi = xgi, gf = xgf, gg = xgg, go = xgo;
#pragma unroll
            for (int qq = 0; qq < 4; qq++) {
                const float* gq = gp + (qq * 16) * 64;
                gi += gq[rI * 64 + b];
                gf += gq[rF * 64 + b];
                gg += gq[rG * 64 + b];
                go += gq[rO * 64 + b];
            }
            float ig = fsig(gi), fg = fsig(gf), gt = ftanh(gg), og = fsig(go);
            cstate = fg * cstate + ig * gt;
            float hv = og * ftanh(cstate);
            asm volatile("st.global.cg.f32 [%0], %1;"
                         :: "l"(hout + (h0 + u2) * 64 + b), "f"(hv) : "memory");
        }
        __syncthreads();   // all hout stores issued + all hs reads done

        // ---- publish: bump global counter (no-return reduction) ---------
        if (tid == 0) {
            asm volatile("fence.acq_rel.gpu;" ::: "memory");
            asm volatile("red.relaxed.gpu.global.add.u32 [%0], %1;"
                         :: "l"(&g_count), "r"(1u) : "memory");
        }
    }
}

// ---------------------------------------------------------------------------
// FC head: out[b][o] = sum_h h_last[h][b] * W_fc[o][h] + b_fc[o]
// warp-per-output, shfl reduction. h_last = g_h buffer 0.
// ---------------------------------------------------------------------------
__global__ void __launch_bounds__(256) k_fc(const float* __restrict__ Wfc,
                                            const float* __restrict__ bfc,
                                            float* __restrict__ out) {
    int g    = blockIdx.x * 8 + (threadIdx.x >> 5);
    int lane = threadIdx.x & 31;
    int o = g >> 6, b = g & 63;
    float s = 0.0f;
#pragma unroll
    for (int j = 0; j < 16; j++) {
        int h = lane + j * 32;
        s += g_h[h * 64 + b] * Wfc[o * 512 + h];
    }
#pragma unroll
    for (int m = 16; m > 0; m >>= 1)
        s += __shfl_xor_sync(0xFFFFFFFFu, s, m);
    if (lane == 0) out[b * 10 + o] = s + bfc[o];
}

// ---------------------------------------------------------------------------
extern "C" void kernel_launch(void* const* d_in, const int* in_sizes, int n_in,
                              void* d_out, int out_size) {
    const float* x    = (const float*)d_in[0];
    const float* W_ih = (const float*)d_in[1];
    const float* W_hh = (const float*)d_in[2];
    const float* b_ih = (const float*)d_in[3];
    const float* b_hh = (const float*)d_in[4];
    const float* W_fc = (const float*)d_in[5];
    const float* b_fc = (const float*)d_in[6];
    float* out = (float*)d_out;

    const int SMEM_REC = 65536 + 131072 + 16384;   // 212992 B (<227KB cap)
    cudaFuncSetAttribute(k_rec, cudaFuncAttributeMaxDynamicSharedMemorySize, SMEM_REC);

    k_init<<<64, 256>>>(b_ih, b_hh);
    k_inproj<<<dim3(16, 2048), 256>>>(x, W_ih);
    k_rec<<<NCTA, 256, SMEM_REC>>>(W_hh);
    k_fc<<<80, 256>>>(W_fc, b_fc, out);
}